// round 4
// baseline (speedup 1.0000x reference)
#include <cuda_runtime.h>
#include <math_constants.h>
#include <stdint.h>

// N=4096 mention-ranking loss. Per-row: bestM (max over masked), maxU (max over
// unmasked strict-lower). CTA b handles rows {b, 4095-b} (uniform work).
// 3-deep cp.async pipeline: mask + ana staged in smem, 16B granules, ana
// aligned-down with uniform shifted-window select (shift = abase&3 per row).

#define NMENT   4096
#define BLOCK   128
#define CHUNK   512                    // floats per stage per stream
#define STAGES  3
#define ANA_TOTAL 8386560LL            // N*(N-1)/2

struct __align__(16) Smem {
    float mbuf[STAGES][CHUNK];         // 2048 B per stage
    float abuf[STAGES][CHUNK + 8];     // 516 used (+shift slack), 2080 B per stage
    float redM[2][BLOCK / 32];
    float redU[2][BLOCK / 32];
};

__device__ __forceinline__ void cp16(uint32_t dst, const float* src, int srcb) {
    asm volatile("cp.async.cg.shared.global [%0], [%1], 16, %2;"
                 :: "r"(dst), "l"(src), "r"(srcb));
}
__device__ __forceinline__ void cp_commit() {
    asm volatile("cp.async.commit_group;" ::: "memory");
}
__device__ __forceinline__ void cp_wait2() {
    asm volatile("cp.async.wait_group %0;" :: "n"(STAGES - 1) : "memory");
}

__device__ __forceinline__ void acc_one(float m, float s, float& bestM, float& maxU)
{
    if (m > 0.5f) bestM = fmaxf(bestM, s);
    else          maxU  = fmaxf(maxU,  s);
}

__global__ __launch_bounds__(BLOCK, 12)
void mention_loss_kernel(const float* __restrict__ eps_scores,
                         const float* __restrict__ ana_scores,
                         const float* __restrict__ mask,
                         const float* __restrict__ link_costs,
                         const float* __restrict__ false_new_cost,
                         float* __restrict__ out)
{
    __shared__ Smem sm;
    const int b   = (int)blockIdx.x;           // 0..2047
    const int tid = (int)threadIdx.x;
    const int warp = tid >> 5;
    const int lane = tid & 31;

    const int row0 = b;
    const int row1 = NMENT - 1 - b;
    const long long ab0 = ((long long)row0 * (row0 - 1)) >> 1;
    const long long ab1 = ((long long)row1 * (row1 - 1)) >> 1;
    const int sh0 = (int)(ab0 & 3);
    const int sh1 = (int)(ab1 & 3);
    const int C0 = (row0 + CHUNK - 1) / CHUNK;
    const int C1 = (row1 + CHUNK - 1) / CHUNK;
    const int total = C0 + C1;                 // >= 4 always

    const uint32_t smbase = (uint32_t)__cvta_generic_to_shared(&sm);
    const uint32_t m_off  = 0;
    const uint32_t a_off  = (uint32_t)(STAGES * CHUNK * 4);

    // --- stage issue: one cp.async group per stage (mask 512f + ana 516f) ---
    auto issue = [&](int t) {
        int r, c, sh; long long ab;
        if (t < C0) { r = row0; c = t;      ab = ab0; sh = sh0; }
        else        { r = row1; c = t - C0; ab = ab1; sh = sh1; }
        const int slot = t % STAGES;

        // mask: always fully in-bounds within row r's 4096 floats
        const float* gm = mask + (size_t)r * NMENT + (size_t)(c * CHUNK + tid * 4);
        cp16(smbase + m_off + (uint32_t)(slot * CHUNK + tid * 4) * 4, gm, 16);

        // ana: aligned-down start; gi is 4-float aligned -> full-16B or fully OOB
        const long long g0 = ab + (long long)c * CHUNK - sh;
        long long gi = g0 + tid * 4;
        int srcb = (gi < ANA_TOTAL) ? 16 : 0;
        if (srcb == 0) gi = 0;
        cp16(smbase + a_off + (uint32_t)(slot * (CHUNK + 8) + tid * 4) * 4,
             ana_scores + gi, srcb);
        if (tid == 0) {
            long long gi2 = g0 + CHUNK;
            int srcb2 = (gi2 < ANA_TOTAL) ? 16 : 0;
            if (srcb2 == 0) gi2 = 0;
            cp16(smbase + a_off + (uint32_t)(slot * (CHUNK + 8) + CHUNK) * 4,
                 ana_scores + gi2, srcb2);
        }
        cp_commit();
    };

    auto consume = [&](int t, int r, int c, int sh, float& bestM, float& maxU) {
        const int slot = t % STAGES;
        const float4 m4 = ((const float4*)sm.mbuf[slot])[tid];
        const float4 a4 = ((const float4*)sm.abuf[slot])[tid];
        const float4 b4 = ((const float4*)sm.abuf[slot])[tid + 1];
        float e0, e1, e2, e3;
        switch (sh) {                      // uniform per row -> no divergence
        case 0:  e0 = a4.x; e1 = a4.y; e2 = a4.z; e3 = a4.w; break;
        case 1:  e0 = a4.y; e1 = a4.z; e2 = a4.w; e3 = b4.x; break;
        case 2:  e0 = a4.z; e1 = a4.w; e2 = b4.x; e3 = b4.y; break;
        default: e0 = a4.w; e1 = b4.x; e2 = b4.y; e3 = b4.z; break;
        }
        const int lim = r - (c * CHUNK + tid * 4);   // valid count among 4
        if (lim > 0) acc_one(m4.x, e0, bestM, maxU);
        if (lim > 1) acc_one(m4.y, e1, bestM, maxU);
        if (lim > 2) acc_one(m4.z, e2, bestM, maxU);
        if (lim > 3) acc_one(m4.w, e3, bestM, maxU);
    };

    float bM0 = -CUDART_INF_F, mU0 = -CUDART_INF_F;
    float bM1 = -CUDART_INF_F, mU1 = -CUDART_INF_F;

    int ti = 0;
    #pragma unroll
    for (int p = 0; p < STAGES; ++p) {     // total >= 4 > STAGES always
        issue(ti); ++ti;
    }
    for (int t = 0; t < total; ++t) {
        cp_wait2();                        // with empty-commit drain: group t done
        __syncthreads();
        if (t < C0) consume(t, row0, t,      sh0, bM0, mU0);
        else        consume(t, row1, t - C0, sh1, bM1, mU1);
        __syncthreads();                   // all readers done before slot reuse
        if (ti < total) { issue(ti); ++ti; }
        else            { cp_commit(); }   // empty group keeps wait accounting exact
    }

    // --- reductions: both rows ---
    #pragma unroll
    for (int off = 16; off > 0; off >>= 1) {
        bM0 = fmaxf(bM0, __shfl_xor_sync(0xffffffffu, bM0, off));
        mU0 = fmaxf(mU0, __shfl_xor_sync(0xffffffffu, mU0, off));
        bM1 = fmaxf(bM1, __shfl_xor_sync(0xffffffffu, bM1, off));
        mU1 = fmaxf(mU1, __shfl_xor_sync(0xffffffffu, mU1, off));
    }
    if (lane == 0) {
        sm.redM[0][warp] = bM0; sm.redU[0][warp] = mU0;
        sm.redM[1][warp] = bM1; sm.redU[1][warp] = mU1;
    }
    __syncthreads();

    if (tid < 2) {
        const int r   = tid;
        const int row = (r == 0) ? row0 : row1;

        float bestM = fmaxf(fmaxf(sm.redM[r][0], sm.redM[r][1]),
                            fmaxf(sm.redM[r][2], sm.redM[r][3]));
        float maxU  = fmaxf(fmaxf(sm.redU[r][0], sm.redU[r][1]),
                            fmaxf(sm.redU[r][2], sm.redU[r][3]));

        const float nonana = __ldg(mask + (size_t)row * NMENT + row);   // diag
        const float e      = __ldg(eps_scores + row);
        if (nonana > 0.5f) bestM = fmaxf(bestM, e);

        const float lc0 = __ldg(link_costs + 0);    // false_link
        const float lc1 = __ldg(link_costs + 1);    // wrong_link
        const float fnc = __ldg(false_new_cost);

        const float row_cost = nonana * lc0 + (1.0f - nonana) * lc1;

        float loss = 0.0f;
        loss = fmaxf(loss, row_cost * (1.0f + maxU - bestM));   // -inf-safe
        const float dcost = (1.0f - nonana) * fnc;
        loss = fmaxf(loss, dcost * (1.0f + e - bestM));

        out[row] = loss;
    }
}

extern "C" void kernel_launch(void* const* d_in, const int* in_sizes, int n_in,
                              void* d_out, int out_size)
{
    const float* eps  = (const float*)d_in[0];
    const float* ana  = (const float*)d_in[1];
    const float* mask = (const float*)d_in[2];
    const float* lc   = (const float*)d_in[3];
    const float* fnc  = (const float*)d_in[4];
    float* out = (float*)d_out;

    mention_loss_kernel<<<NMENT / 2, BLOCK>>>(eps, ana, mask, lc, fnc, out);
}

// round 6
// speedup vs baseline: 1.1800x; 1.1800x over previous
#include <cuda_runtime.h>
#include <math_constants.h>
#include <stdint.h>

// N=4096 mention-ranking loss, one streaming pass, row-paired CTAs {b, 4095-b}.
// 256-bit loads (LDG.256) with L2::evict_last on both streams (sm_103a only
// allows the evict hint on .v8.b32). ana misalignment: two aligned v8 blocks +
// uniform window select (sh = abase & 7, constant per row).

#define NMENT 4096
#define BLOCK 128
#define ANA_TOTAL 8386560   // N*(N-1)/2

struct F8 { float f[8]; };

__device__ __forceinline__ F8 ldg_el8(const float* p)
{
    uint32_t a0,a1,a2,a3,a4,a5,a6,a7;
    asm("ld.global.nc.L2::evict_last.v8.b32 {%0,%1,%2,%3,%4,%5,%6,%7}, [%8];"
        : "=r"(a0),"=r"(a1),"=r"(a2),"=r"(a3),
          "=r"(a4),"=r"(a5),"=r"(a6),"=r"(a7) : "l"(p));
    F8 r;
    r.f[0]=__uint_as_float(a0); r.f[1]=__uint_as_float(a1);
    r.f[2]=__uint_as_float(a2); r.f[3]=__uint_as_float(a3);
    r.f[4]=__uint_as_float(a4); r.f[5]=__uint_as_float(a5);
    r.f[6]=__uint_as_float(a6); r.f[7]=__uint_as_float(a7);
    return r;
}

__device__ __forceinline__ void acc_one(float m, float s, float& bestM, float& maxU)
{
    if (m > 0.5f) bestM = fmaxf(bestM, s);
    else          maxU  = fmaxf(maxU,  s);
}

// Select e[0..7] = concat(a,b)[sh .. sh+8). sh uniform per row (0..7).
__device__ __forceinline__ void select8(const F8& a, const F8& b, int sh, float e[8])
{
    switch (sh) {
    case 0: e[0]=a.f[0];e[1]=a.f[1];e[2]=a.f[2];e[3]=a.f[3];e[4]=a.f[4];e[5]=a.f[5];e[6]=a.f[6];e[7]=a.f[7]; break;
    case 1: e[0]=a.f[1];e[1]=a.f[2];e[2]=a.f[3];e[3]=a.f[4];e[4]=a.f[5];e[5]=a.f[6];e[6]=a.f[7];e[7]=b.f[0]; break;
    case 2: e[0]=a.f[2];e[1]=a.f[3];e[2]=a.f[4];e[3]=a.f[5];e[4]=a.f[6];e[5]=a.f[7];e[6]=b.f[0];e[7]=b.f[1]; break;
    case 3: e[0]=a.f[3];e[1]=a.f[4];e[2]=a.f[5];e[3]=a.f[6];e[4]=a.f[7];e[5]=b.f[0];e[6]=b.f[1];e[7]=b.f[2]; break;
    case 4: e[0]=a.f[4];e[1]=a.f[5];e[2]=a.f[6];e[3]=a.f[7];e[4]=b.f[0];e[5]=b.f[1];e[6]=b.f[2];e[7]=b.f[3]; break;
    case 5: e[0]=a.f[5];e[1]=a.f[6];e[2]=a.f[7];e[3]=b.f[0];e[4]=b.f[1];e[5]=b.f[2];e[6]=b.f[3];e[7]=b.f[4]; break;
    case 6: e[0]=a.f[6];e[1]=a.f[7];e[2]=b.f[0];e[3]=b.f[1];e[4]=b.f[2];e[5]=b.f[3];e[6]=b.f[4];e[7]=b.f[5]; break;
    default:e[0]=a.f[7];e[1]=b.f[0];e[2]=b.f[1];e[3]=b.f[2];e[4]=b.f[3];e[5]=b.f[4];e[6]=b.f[5];e[7]=b.f[6]; break;
    }
}

__global__ __launch_bounds__(BLOCK, 12)
void mention_loss_kernel(const float* __restrict__ eps_scores,
                         const float* __restrict__ ana_scores,
                         const float* __restrict__ mask,
                         const float* __restrict__ link_costs,
                         const float* __restrict__ false_new_cost,
                         float* __restrict__ out)
{
    const int b   = (int)blockIdx.x;        // 0..2047
    const int tid = (int)threadIdx.x;
    const int warp = tid >> 5;
    const int lane = tid & 31;

    __shared__ float sM[2][BLOCK / 32];
    __shared__ float sU[2][BLOCK / 32];

    const float lc0 = __ldg(link_costs + 0);    // false_link
    const float lc1 = __ldg(link_costs + 1);    // wrong_link
    const float fnc = __ldg(false_new_cost);

    #pragma unroll
    for (int r = 0; r < 2; ++r) {
        const int row = (r == 0) ? b : (NMENT - 1 - b);

        const float* __restrict__ mrow = mask + (size_t)row * NMENT;   // 32B-aligned
        const long long abase = ((long long)row * (row - 1)) >> 1;
        const float* __restrict__ arow = ana_scores + abase;
        const int sh = (int)(abase & 7);

        float bestM = -CUDART_INF_F;
        float maxU  = -CUDART_INF_F;

        // Main loop: 8-element groups with j0+16 <= row (both ana v8 blocks
        // are then guaranteed in-bounds: abase + j0 + 16 <= abase + row <= TOTAL).
        const int nv = (row >= 16) ? ((row - 8) >> 3) : 0;

        #pragma unroll 2
        for (int v = tid; v < nv; v += BLOCK) {
            const int j0 = v << 3;
            const F8 m  = ldg_el8(mrow + j0);
            const float* ga = arow + j0 - sh;       // 32B-aligned
            const F8 a  = ldg_el8(ga);
            const F8 b8 = ldg_el8(ga + 8);
            float e[8];
            select8(a, b8, sh, e);
            #pragma unroll
            for (int k = 0; k < 8; ++k)
                acc_one(m.f[k], e[k], bestM, maxU);
        }
        // Scalar tail: j in [nv*8, row)
        for (int j = (nv << 3) + tid; j < row; j += BLOCK) {
            acc_one(__ldg(mrow + j), __ldg(arow + j), bestM, maxU);
        }

        // Warp reduction
        #pragma unroll
        for (int off = 16; off > 0; off >>= 1) {
            bestM = fmaxf(bestM, __shfl_xor_sync(0xffffffffu, bestM, off));
            maxU  = fmaxf(maxU,  __shfl_xor_sync(0xffffffffu, maxU,  off));
        }
        if (lane == 0) { sM[r][warp] = bestM; sU[r][warp] = maxU; }
    }

    __syncthreads();

    // One warp finalizes both rows (4 partials each).
    if (warp == 0 && lane < 2) {
        const int r = lane;
        const int row = (r == 0) ? b : (NMENT - 1 - b);

        float bestM = fmaxf(fmaxf(sM[r][0], sM[r][1]), fmaxf(sM[r][2], sM[r][3]));
        float maxU  = fmaxf(fmaxf(sU[r][0], sU[r][1]), fmaxf(sU[r][2], sU[r][3]));

        const float nonana = __ldg(mask + (size_t)row * NMENT + row);   // diag
        const float e      = __ldg(eps_scores + row);
        if (nonana > 0.5f) bestM = fmaxf(bestM, e);

        const float row_cost = nonana * lc0 + (1.0f - nonana) * lc1;

        float loss = 0.0f;
        loss = fmaxf(loss, row_cost * (1.0f + maxU - bestM));   // -inf-safe
        const float dcost = (1.0f - nonana) * fnc;
        loss = fmaxf(loss, dcost * (1.0f + e - bestM));

        out[row] = loss;
    }
}

extern "C" void kernel_launch(void* const* d_in, const int* in_sizes, int n_in,
                              void* d_out, int out_size)
{
    const float* eps  = (const float*)d_in[0];
    const float* ana  = (const float*)d_in[1];
    const float* mask = (const float*)d_in[2];
    const float* lc   = (const float*)d_in[3];
    const float* fnc  = (const float*)d_in[4];
    float* out = (float*)d_out;

    mention_loss_kernel<<<NMENT / 2, BLOCK>>>(eps, ana, mask, lc, fnc, out);
}